// round 4
// baseline (speedup 1.0000x reference)
#include <cuda_runtime.h>
#include <math.h>

// Problem constants
#define FQ 8
#define TQ 5
#define ZQ 16
#define YQ 96
#define XQ 96
#define NRAYS 32768
#define KSAMP 128
#define NEARP 0.01f

#define PLANE (YQ*XQ)          // 9216
#define VOLT  (ZQ*PLANE)       // per-(t) scalar volume: 16*9216
#define TOTRAYS (TQ*NRAYS)     // 163840

// Scratch (allocation-free: __device__ globals)
__device__ float    g_wf[16*128*27];   // folded weights [z_out][ci][27]
__device__ float    g_bf[16];          // folded bias
__device__ float    g_S[TQ*VOLT];      // scalar density-logit volume [t][z][y][x]
__device__ unsigned g_mn[TQ];          // per-t min(starts) bits (positive floats)
__device__ unsigned g_mx[TQ];          // per-t max(starts) bits

// ---------------------------------------------------------------------------
__global__ void k_init() {
    int i = threadIdx.x;
    if (i < TQ) { g_mn[i] = 0x7F800000u; g_mx[i] = 0u; }
}

// Fold dens_w into conv weights: w'[z,ci,k] = sum_f dens_w[f]*conv_w[f*16+z, ci, k]
__global__ void k_fold(const float* __restrict__ cw, const float* __restrict__ cb,
                       const float* __restrict__ dw) {
    int i = blockIdx.x * blockDim.x + threadIdx.x;
    if (i < 16*128*27) {
        int z = i / (128*27);
        int r = i - z*(128*27);          // ci*27 + k
        float s = 0.f;
        #pragma unroll
        for (int f = 0; f < 8; f++)
            s += dw[f] * cw[(f*16 + z)*(128*27) + r];
        g_wf[i] = s;
    }
    if (i < 16) {
        float s = 0.f;
        #pragma unroll
        for (int f = 0; f < 8; f++) s += dw[f] * cb[f*16 + i];
        g_bf[i] = s;
    }
}

// ---------------------------------------------------------------------------
// Direct 3x3x3 conv, 128 in-ch -> 16 out-ch (z), fused with dens_w fold.
// Tile: 32(x) x 8(y), one t, half the z-outputs (8) per block.
// 128 threads; each thread: 2 x-positions x 8 z accumulators.
__global__ void __launch_bounds__(128) k_conv(const float* __restrict__ vol) {
    __shared__ float s_in[3*10*34];      // (t-1..t+1) x (y0-1..y0+8) x (x0-1..x0+32)
    __shared__ float s_w[8*27];

    const int bz    = blockIdx.z;        // 0..9 = t*2 + zhalf
    const int t     = bz >> 1;
    const int zbase = (bz & 1) * 8;
    const int y0    = blockIdx.y * 8;
    const int x0    = blockIdx.x * 32;
    const int tid   = threadIdx.x;
    const int lx    = (tid & 15) * 2;
    const int ly    = tid >> 4;

    float acc0[8], acc1[8];
    #pragma unroll
    for (int z = 0; z < 8; z++) { acc0[z] = 0.f; acc1[z] = 0.f; }

    for (int ci = 0; ci < 128; ci++) {
        __syncthreads();
        // weights for this ci: 8*27
        for (int i = tid; i < 8*27; i += 128) {
            int z = i / 27, k = i - z*27;
            s_w[i] = g_wf[((zbase + z)*128 + ci)*27 + k];
        }
        // input patch: ci = f*16 + zin in the reshaped layout
        const int f = ci >> 4, zin = ci & 15;
        const float* base = vol + (size_t)f*(TQ*VOLT) + (size_t)zin*PLANE;
        for (int i = tid; i < 3*10*34; i += 128) {
            int p  = i / 340;
            int r  = i - p*340;
            int ry = r / 34, rx = r - ry*34;
            int gt = t - 1 + p, gy = y0 - 1 + ry, gx = x0 - 1 + rx;
            float v = 0.f;
            if ((unsigned)gt < 5u && (unsigned)gy < 96u && (unsigned)gx < 96u)
                v = base[(size_t)gt*VOLT + gy*96 + gx];
            s_in[i] = v;
        }
        __syncthreads();

        float rin[3][3][4];
        #pragma unroll
        for (int p = 0; p < 3; p++)
            #pragma unroll
            for (int dy = 0; dy < 3; dy++)
                #pragma unroll
                for (int dx = 0; dx < 4; dx++)
                    rin[p][dy][dx] = s_in[(p*10 + ly + dy)*34 + lx + dx];

        #pragma unroll
        for (int z = 0; z < 8; z++) {
            #pragma unroll
            for (int p = 0; p < 3; p++)
                #pragma unroll
                for (int dy = 0; dy < 3; dy++)
                    #pragma unroll
                    for (int dx = 0; dx < 3; dx++) {
                        float w = s_w[z*27 + (p*3 + dy)*3 + dx];
                        acc0[z] = fmaf(rin[p][dy][dx    ], w, acc0[z]);
                        acc1[z] = fmaf(rin[p][dy][dx + 1], w, acc1[z]);
                    }
        }
    }

    const int oy = y0 + ly, ox = x0 + lx;
    #pragma unroll
    for (int z = 0; z < 8; z++) {
        float b = g_bf[zbase + z];
        int idx = ((t*16 + zbase + z)*96 + oy)*96 + ox;
        g_S[idx]     = acc0[z] + b;
        g_S[idx + 1] = acc1[z] + b;
    }
}

// ---------------------------------------------------------------------------
// One thread per ray: AABB near/far, 128 trilinear samples of S, softplus,
// transmittance accumulation, expected depth. Also reduces per-t min/max of
// `starts` (warp redux + 1 atomic per warp).
__global__ void __launch_bounds__(256) k_march(const float* __restrict__ ro,
                                               const float* __restrict__ rd,
                                               const float* __restrict__ db_,
                                               float* __restrict__ out) {
    const int gid = blockIdx.x * 256 + threadIdx.x;   // 640 * 256 == 163840 exact
    const int t   = gid >> 15;

    const float ox = ro[gid*3+0], oy = ro[gid*3+1], oz = ro[gid*3+2];
    const float dx = rd[gid*3+0], dy = rd[gid*3+1], dz = rd[gid*3+2];
    const float db = db_[0];

    float t1, t2;
    t1 = (0.f - ox)/dx; t2 = (1.f - ox)/dx;
    float nearv = fminf(t1, t2), farv = fmaxf(t1, t2);
    t1 = (0.f - oy)/dy; t2 = (1.f - oy)/dy;
    nearv = fmaxf(nearv, fminf(t1, t2)); farv = fminf(farv, fmaxf(t1, t2));
    t1 = (0.f - oz)/dz; t2 = (1.f - oz)/dz;
    nearv = fmaxf(nearv, fminf(t1, t2)); farv = fminf(farv, fmaxf(t1, t2));
    nearv = fmaxf(nearv, NEARP);
    farv  = fmaxf(farv, nearv + 1e-6f);
    const float fr = farv - nearv;

    // per-t reduction of starts.min()/starts.max()
    {
        unsigned un = __float_as_uint(nearv);
        unsigned ux = __float_as_uint(nearv + (127.f/128.f)*fr);
        un = __reduce_min_sync(0xFFFFFFFFu, un);
        ux = __reduce_max_sync(0xFFFFFFFFu, ux);
        if ((threadIdx.x & 31) == 0) {
            atomicMin(&g_mn[t], un);
            atomicMax(&g_mx[t], ux);
        }
    }

    const float* __restrict__ St = g_S + t*VOLT;
    float e = 1.f, num = 0.f, den = 0.f;

    #pragma unroll 4
    for (int k = 0; k < KSAMP; k++) {
        float sk  = fmaf((float)k       * (1.f/128.f), fr, nearv);
        float ek  = fmaf((float)(k + 1) * (1.f/128.f), fr, nearv);
        float mid = 0.5f*(sk + ek);
        float dl  = ek - sk;

        float gx = __saturatef(fmaf(dx, mid, ox)) * 95.f;
        float gy = __saturatef(fmaf(dy, mid, oy)) * 95.f;
        float gz = __saturatef(fmaf(dz, mid, oz)) * 15.f;
        int ix = (int)gx, iy = (int)gy, iz = (int)gz;
        float fx = gx - ix, fy = gy - iy, fz = gz - iz;
        int ix1 = min(ix + 1, 95), iy1 = min(iy + 1, 95), iz1 = min(iz + 1, 15);

        int r00 = (iz *96 + iy )*96;
        int r01 = (iz *96 + iy1)*96;
        int r10 = (iz1*96 + iy )*96;
        int r11 = (iz1*96 + iy1)*96;
        float v000 = St[r00 + ix], v001 = St[r00 + ix1];
        float v010 = St[r01 + ix], v011 = St[r01 + ix1];
        float v100 = St[r10 + ix], v101 = St[r10 + ix1];
        float v110 = St[r11 + ix], v111 = St[r11 + ix1];

        float c00 = v000 + fx*(v001 - v000);
        float c01 = v010 + fx*(v011 - v010);
        float c10 = v100 + fx*(v101 - v100);
        float c11 = v110 + fx*(v111 - v110);
        float c0  = c00 + fy*(c01 - c00);
        float c1  = c10 + fy*(c11 - c10);
        float s   = c0 + fz*(c1 - c0) + db;

        // softplus = logaddexp(s, 0)
        float dens = (s > 0.f) ? (s + log1pf(expf(-s))) : log1pf(expf(s));
        float dd   = dens * dl;
        float en   = e * expf(-dd);
        float w    = e - en;                 // alpha * trans
        num = fmaf(w, sk, num);
        den += w;
        e = en;
    }

    out[gid] = num / (den + 1e-10f);
}

__global__ void __launch_bounds__(256) k_clip(float* __restrict__ out) {
    const int gid = blockIdx.x * 256 + threadIdx.x;
    const int t   = gid >> 15;
    float mn = __uint_as_float(g_mn[t]);
    float mx = __uint_as_float(g_mx[t]);
    out[gid] = fminf(fmaxf(out[gid], mn), mx);
}

// ---------------------------------------------------------------------------
extern "C" void kernel_launch(void* const* d_in, const int* in_sizes, int n_in,
                              void* d_out, int out_size) {
    const float* vol = (const float*)d_in[0];   // [1,8,5,16,96,96]
    const float* ro  = (const float*)d_in[1];   // [5,32768,3]
    const float* rd  = (const float*)d_in[2];   // [5,32768,3]
    const float* cw  = (const float*)d_in[3];   // [128,128,3,3,3]
    const float* cb  = (const float*)d_in[4];   // [128]
    const float* dw  = (const float*)d_in[5];   // [8,1]
    const float* db  = (const float*)d_in[6];   // [1]
    float* out = (float*)d_out;                 // [5,32768,1]

    k_init<<<1, 32>>>();
    k_fold<<<(16*128*27 + 255)/256, 256>>>(cw, cb, dw);
    k_conv<<<dim3(3, 12, 10), 128>>>(vol);
    k_march<<<TOTRAYS/256, 256>>>(ro, rd, db, out);
    k_clip<<<TOTRAYS/256, 256>>>(out);
}

// round 8
// speedup vs baseline: 1.4977x; 1.4977x over previous
#include <cuda_runtime.h>
#include <math.h>

// Problem constants
#define FQ 8
#define TQ 5
#define ZQ 16
#define YQ 96
#define XQ 96
#define NRAYS 32768
#define KSAMP 128
#define NEARP 0.01f

#define PLANE (YQ*XQ)          // 9216
#define VOLT  (ZQ*PLANE)       // per-(t) scalar volume: 147456
#define TOTRAYS (TQ*NRAYS)     // 163840

// Scratch (allocation-free: __device__ globals)
__device__ float    g_wf[16*128*27];   // folded weights [z_out][ci][27]
__device__ float    g_bf[16];          // folded bias
__device__ float    g_S[TQ*VOLT];      // scalar density-logit volume [t][z][y][x]
__device__ float4   g_S4[TQ*VOLT];     // quad-packed: (S[z,x], S[z,x1], S[z1,x], S[z1,x1])
__device__ unsigned g_mn[TQ];          // per-t min(starts) bits (positive floats)
__device__ unsigned g_mx[TQ];          // per-t max(starts) bits

// ---------------------------------------------------------------------------
// f32x2 packed helpers (sm_103a)
__device__ __forceinline__ unsigned long long pack_dup(float v) {
    unsigned long long r;
    asm("mov.b64 %0, {%1, %1};" : "=l"(r) : "f"(v));
    return r;
}
#define FFMA2(acc, a, b) \
    asm("fma.rn.f32x2 %0, %1, %2, %0;" : "+l"(acc) : "l"(a), "l"(b))

__device__ __forceinline__ float2 unpack2(unsigned long long v) {
    float2 r;
    asm("mov.b64 {%0, %1}, %2;" : "=f"(r.x), "=f"(r.y) : "l"(v));
    return r;
}

// ---------------------------------------------------------------------------
__global__ void k_init() {
    int i = threadIdx.x;
    if (i < TQ) { g_mn[i] = 0x7F800000u; g_mx[i] = 0u; }
}

// Fold dens_w into conv weights: w'[z,ci,k] = sum_f dens_w[f]*conv_w[f*16+z, ci, k]
__global__ void k_fold(const float* __restrict__ cw, const float* __restrict__ cb,
                       const float* __restrict__ dw) {
    int i = blockIdx.x * blockDim.x + threadIdx.x;
    if (i < 16*128*27) {
        int z = i / (128*27);
        int r = i - z*(128*27);          // ci*27 + k
        float s = 0.f;
        #pragma unroll
        for (int f = 0; f < 8; f++)
            s += dw[f] * cw[(f*16 + z)*(128*27) + r];
        g_wf[i] = s;
    }
    if (i < 16) {
        float s = 0.f;
        #pragma unroll
        for (int f = 0; f < 8; f++) s += dw[f] * cb[f*16 + i];
        g_bf[i] = s;
    }
}

// ---------------------------------------------------------------------------
// Direct 3x3x3 conv, 128 in-ch -> 16 out-ch (z), packed f32x2 over z-pairs.
// Tile: 32(x) x 8(y), one t, ALL 16 z per block.
// 128 threads; each thread: 2 x-positions x 8 z-pair (f32x2) accumulators.
__global__ void __launch_bounds__(128) k_conv(const float* __restrict__ vol) {
    __shared__ float  s_in[3*10*34];     // (t-1..t+1) x (y0-1..y0+8) x (x0-1..x0+32)
    __shared__ float2 s_w2[27*8];        // [tap][zpair], z contiguous -> LDS.64

    float* sw = (float*)s_w2;            // sw[tap*16 + z]

    const int t   = blockIdx.z;
    const int y0  = blockIdx.y * 8;
    const int x0  = blockIdx.x * 32;
    const int tid = threadIdx.x;
    const int lx  = (tid & 15) * 2;
    const int ly  = tid >> 4;

    unsigned long long acc0[8], acc1[8];
    #pragma unroll
    for (int zp = 0; zp < 8; zp++) { acc0[zp] = 0ull; acc1[zp] = 0ull; }

    for (int ci = 0; ci < 128; ci++) {
        __syncthreads();
        // weights for this ci: sw[tap*16 + z] = g_wf[(z*128+ci)*27 + tap]
        for (int i = tid; i < 27*16; i += 128) {
            int k = i >> 4, z = i & 15;
            sw[i] = g_wf[(z*128 + ci)*27 + k];
        }
        // input patch: ci = f*16 + zin in the reshaped layout
        const int f = ci >> 4, zin = ci & 15;
        const float* base = vol + (size_t)f*(TQ*VOLT) + (size_t)zin*PLANE;
        for (int i = tid; i < 3*10*34; i += 128) {
            int p  = i / 340;
            int r  = i - p*340;
            int ry = r / 34, rx = r - ry*34;
            int gt = t - 1 + p, gy = y0 - 1 + ry, gx = x0 - 1 + rx;
            float v = 0.f;
            if ((unsigned)gt < 5u && (unsigned)gy < 96u && (unsigned)gx < 96u)
                v = base[(size_t)gt*VOLT + gy*96 + gx];
            s_in[i] = v;
        }
        __syncthreads();

        const unsigned long long* w64 = (const unsigned long long*)s_w2;

        #pragma unroll
        for (int p = 0; p < 3; p++) {
            // dup-packed inputs for this t-plane: dx 0..3 covers both x-outputs
            unsigned long long vv[3][4];
            #pragma unroll
            for (int dy = 0; dy < 3; dy++)
                #pragma unroll
                for (int dx = 0; dx < 4; dx++)
                    vv[dy][dx] = pack_dup(s_in[(p*10 + ly + dy)*34 + lx + dx]);

            #pragma unroll
            for (int dy = 0; dy < 3; dy++)
                #pragma unroll
                for (int dx = 0; dx < 3; dx++) {
                    const int tap = (p*3 + dy)*3 + dx;
                    #pragma unroll
                    for (int zp = 0; zp < 8; zp++) {
                        unsigned long long w2 = w64[tap*8 + zp];
                        FFMA2(acc0[zp], vv[dy][dx    ], w2);
                        FFMA2(acc1[zp], vv[dy][dx + 1], w2);
                    }
                }
        }
    }

    const int oy = y0 + ly, ox = x0 + lx;
    #pragma unroll
    for (int zp = 0; zp < 8; zp++) {
        float2 a0 = unpack2(acc0[zp]);
        float2 a1 = unpack2(acc1[zp]);
        float b0 = g_bf[2*zp], b1 = g_bf[2*zp + 1];
        int i0 = ((t*16 + 2*zp    )*96 + oy)*96 + ox;
        int i1 = ((t*16 + 2*zp + 1)*96 + oy)*96 + ox;
        g_S[i0]     = a0.x + b0;
        g_S[i0 + 1] = a1.x + b0;
        g_S[i1]     = a0.y + b1;
        g_S[i1 + 1] = a1.y + b1;
    }
}

// ---------------------------------------------------------------------------
// Quad-pack the scalar volume: one float4 per voxel holds the (z,z1)x(x,x1)
// corner set, with x+1 / z+1 clamps baked in.
__global__ void __launch_bounds__(256) k_pack() {
    int i = blockIdx.x * 256 + threadIdx.x;     // 2880 * 256 == TQ*VOLT exact
    int x = i % 96;
    int r = i / 96;
    int y = r % 96; r /= 96;
    int z = r % 16;
    int t = r / 16;
    const float* St = g_S + t*VOLT;
    int x1 = min(x + 1, 95), z1 = min(z + 1, 15);
    float4 v;
    v.x = St[(z *96 + y)*96 + x ];
    v.y = St[(z *96 + y)*96 + x1];
    v.z = St[(z1*96 + y)*96 + x ];
    v.w = St[(z1*96 + y)*96 + x1];
    g_S4[i] = v;
}

// ---------------------------------------------------------------------------
// One thread per ray: AABB near/far, 128 trilinear samples (2 LDG.128 each),
// fast softplus/exp, transmittance accumulation, expected depth.
__global__ void __launch_bounds__(128) k_march(const float* __restrict__ ro,
                                               const float* __restrict__ rd,
                                               const float* __restrict__ db_,
                                               float* __restrict__ out) {
    const int gid = blockIdx.x * 128 + threadIdx.x;   // 1280 * 128 == 163840
    const int t   = gid >> 15;

    const float ox = ro[gid*3+0], oy = ro[gid*3+1], oz = ro[gid*3+2];
    const float dx = rd[gid*3+0], dy = rd[gid*3+1], dz = rd[gid*3+2];
    const float db = db_[0];

    float t1, t2;
    t1 = (0.f - ox)/dx; t2 = (1.f - ox)/dx;
    float nearv = fminf(t1, t2), farv = fmaxf(t1, t2);
    t1 = (0.f - oy)/dy; t2 = (1.f - oy)/dy;
    nearv = fmaxf(nearv, fminf(t1, t2)); farv = fminf(farv, fmaxf(t1, t2));
    t1 = (0.f - oz)/dz; t2 = (1.f - oz)/dz;
    nearv = fmaxf(nearv, fminf(t1, t2)); farv = fminf(farv, fmaxf(t1, t2));
    nearv = fmaxf(nearv, NEARP);
    farv  = fmaxf(farv, nearv + 1e-6f);
    const float fr = farv - nearv;

    // per-t reduction of starts.min()/starts.max()
    {
        unsigned un = __float_as_uint(nearv);
        unsigned ux = __float_as_uint(nearv + (127.f/128.f)*fr);
        un = __reduce_min_sync(0xFFFFFFFFu, un);
        ux = __reduce_max_sync(0xFFFFFFFFu, ux);
        if ((threadIdx.x & 31) == 0) {
            atomicMin(&g_mn[t], un);
            atomicMax(&g_mx[t], ux);
        }
    }

    const float4* __restrict__ St4 = g_S4 + t*VOLT;
    float e = 1.f, num = 0.f, den = 0.f;

    #pragma unroll 4
    for (int k = 0; k < KSAMP; k++) {
        float sk  = fmaf((float)k       * (1.f/128.f), fr, nearv);
        float ek  = fmaf((float)(k + 1) * (1.f/128.f), fr, nearv);
        float mid = 0.5f*(sk + ek);
        float dl  = ek - sk;

        float gx = __saturatef(fmaf(dx, mid, ox)) * 95.f;
        float gy = __saturatef(fmaf(dy, mid, oy)) * 95.f;
        float gz = __saturatef(fmaf(dz, mid, oz)) * 15.f;
        int ix = (int)gx, iy = (int)gy, iz = (int)gz;
        float fx = gx - ix, fy = gy - iy, fz = gz - iz;

        int row = (iz*96 + iy)*96 + ix;
        float4 A  = St4[row];                            // (z0x0, z0x1, z1x0, z1x1) @ y0
        float4 Bv = St4[row + ((iy < 95) ? 96 : 0)];     // same @ y1

        float c00 = fmaf(fx, A.y  - A.x,  A.x);   // z0 y0
        float c10 = fmaf(fx, A.w  - A.z,  A.z);   // z1 y0
        float c01 = fmaf(fx, Bv.y - Bv.x, Bv.x);  // z0 y1
        float c11 = fmaf(fx, Bv.w - Bv.z, Bv.z);  // z1 y1
        float c0  = fmaf(fy, c01 - c00, c00);
        float c1  = fmaf(fy, c11 - c10, c10);
        float s   = fmaf(fz, c1 - c0, c0) + db;

        // softplus(s) = max(s,0) + log(1 + exp(-|s|))  (fast MUFU path)
        float dens = fmaxf(s, 0.f) + __logf(1.f + __expf(-fabsf(s)));
        float dd   = dens * dl;
        float en   = e * __expf(-dd);
        float w    = e - en;                 // alpha * trans
        num = fmaf(w, sk, num);
        den += w;
        e = en;
    }

    out[gid] = num / (den + 1e-10f);
}

__global__ void __launch_bounds__(256) k_clip(float* __restrict__ out) {
    const int gid = blockIdx.x * 256 + threadIdx.x;
    const int t   = gid >> 15;
    float mn = __uint_as_float(g_mn[t]);
    float mx = __uint_as_float(g_mx[t]);
    out[gid] = fminf(fmaxf(out[gid], mn), mx);
}

// ---------------------------------------------------------------------------
extern "C" void kernel_launch(void* const* d_in, const int* in_sizes, int n_in,
                              void* d_out, int out_size) {
    const float* vol = (const float*)d_in[0];   // [1,8,5,16,96,96]
    const float* ro  = (const float*)d_in[1];   // [5,32768,3]
    const float* rd  = (const float*)d_in[2];   // [5,32768,3]
    const float* cw  = (const float*)d_in[3];   // [128,128,3,3,3]
    const float* cb  = (const float*)d_in[4];   // [128]
    const float* dw  = (const float*)d_in[5];   // [8,1]
    const float* db  = (const float*)d_in[6];   // [1]
    float* out = (float*)d_out;                 // [5,32768,1]

    k_init<<<1, 32>>>();
    k_fold<<<(16*128*27 + 255)/256, 256>>>(cw, cb, dw);
    k_conv<<<dim3(3, 12, 5), 128>>>(vol);
    k_pack<<<(TQ*VOLT)/256, 256>>>();
    k_march<<<TOTRAYS/128, 128>>>(ro, rd, db, out);
    k_clip<<<TOTRAYS/256, 256>>>(out);
}